// round 3
// baseline (speedup 1.0000x reference)
#include <cuda_runtime.h>
#include <cstdint>

// ESN recurrence, persistent single-kernel design.
// T=1000, B=64, I=80, H=1024, LEAK=0.5.
//   a      = x[t] @ W_ih^T + h @ W_hh^T
//   h_new  = 0.5*h + 0.5*tanh(a)   (rows with t < len[b] advance, others hold)
//   out[t] = h_new * valid (zeros past length)
//
// 128 persistent CTAs x 256 threads (one wave). CTA owns 8 h-columns.
// W slices in SMEM duplicated as f32x2; h double-buffered in device global,
// [H][B/2] packed u64 (batch pair per lane); grid barrier per step.

#define BB    64
#define II    80
#define HH    1024
#define NCTA  128
#define HC    8
#define NTHR  256
#define NWARP 8
#define KPW   (HH / NWARP)   // 128
#define IPW   (II / NWARP)   // 10
#define T_MAX 1024

typedef unsigned long long u64;

__device__ u64 g_h[2][HH * (BB / 2)];
__device__ __align__(16) float g_xT[T_MAX * II * BB];   // [t][i][b]
__device__ unsigned g_bar_count = 0;
__device__ volatile unsigned g_bar_gen = 0;

__device__ __forceinline__ u64 ffma2(u64 a, u64 b, u64 c) {
    u64 d; asm("fma.rn.f32x2 %0, %1, %2, %3;" : "=l"(d) : "l"(a), "l"(b), "l"(c)); return d;
}
__device__ __forceinline__ u64 fadd2(u64 a, u64 b) {
    u64 d; asm("add.rn.f32x2 %0, %1, %2;" : "=l"(d) : "l"(a), "l"(b)); return d;
}
__device__ __forceinline__ u64 pack2(float lo, float hi) {
    u64 d; asm("mov.b64 %0, {%1, %2};" : "=l"(d) : "f"(lo), "f"(hi)); return d;
}
__device__ __forceinline__ float lo2(u64 v) { return __uint_as_float((unsigned)v); }
__device__ __forceinline__ float hi2(u64 v) { return __uint_as_float((unsigned)(v >> 32)); }

__device__ __forceinline__ void grid_barrier() {
    __syncthreads();
    if (threadIdx.x == 0) {
        __threadfence();                       // publish h stores
        unsigned g = g_bar_gen;                // read BEFORE arriving
        if (atomicAdd(&g_bar_count, 1u) == gridDim.x - 1u) {
            g_bar_count = 0;
            __threadfence();
            g_bar_gen = g + 1u;
        } else {
            while (g_bar_gen == g) { }
        }
        __threadfence();                       // acquire
    }
    __syncthreads();
}

// dynamic SMEM layout:
//  [0,65536)       Ws   : W_hh slice [k][8j] dup f32x2 (u64)
//  [65536,70656)   Wihs : W_ih slice [i][8j] dup f32x2 (u64)
//  [70656,87040)   red  : [8 warp][8 j][32 lane] u64   (aliased w/ xs)
//  [70656,91392)   xs   : [64][81] float transpose scratch (staging only)
//  [87040,89088)   outs : [8 j][64 b] float
#define SMEM_BYTES 91392

extern "C" __global__ void __launch_bounds__(NTHR, 1)
esn_kernel(const float* __restrict__ x, const int* __restrict__ lengths,
           const float* __restrict__ W_ih, const float* __restrict__ W_hh,
           float* __restrict__ out, int T)
{
    extern __shared__ unsigned char smem[];
    u64*   Ws   = (u64*)smem;
    u64*   Wihs = (u64*)(smem + 65536);
    u64*   red  = (u64*)(smem + 70656);
    float* xs   = (float*)(smem + 70656);
    float* outs = (float*)(smem + 87040);

    const int tid = threadIdx.x;
    const int w   = tid >> 5;
    const int l   = tid & 31;
    const int j0  = blockIdx.x * HC;

    // ---- one-time staging ----
    for (int idx = tid; idx < HH * HC; idx += NTHR) {
        int k = idx >> 3, jj = idx & 7;
        float v = W_hh[(size_t)(j0 + jj) * HH + k];
        Ws[k * 8 + jj] = pack2(v, v);
    }
    for (int idx = tid; idx < II * HC; idx += NTHR) {
        int i = idx >> 3, jj = idx & 7;
        float v = W_ih[(j0 + jj) * II + i];
        Wihs[i * 8 + jj] = pack2(v, v);
    }
    for (int idx = tid; idx < HC * (BB / 2); idx += NTHR)
        g_h[0][j0 * (BB / 2) + idx] = 0ull;

    // transpose x[t][b][i] -> g_xT[t][i][b]
    for (int tt = blockIdx.x; tt < T; tt += NCTA) {
        __syncthreads();
        const float4* src = (const float4*)(x + (size_t)tt * BB * II);
        for (int idx = tid; idx < (BB * II) / 4; idx += NTHR) {
            float4 v = src[idx];
            int base = idx * 4;
            int b = base / II, i = base % II;     // II%4==0: row-local
            float* dst = &xs[b * 81 + i];
            dst[0] = v.x; dst[1] = v.y; dst[2] = v.z; dst[3] = v.w;
        }
        __syncthreads();
        for (int idx = tid; idx < BB * II; idx += NTHR) {
            int i = idx >> 6, b = idx & 63;
            g_xT[((size_t)tt * II + i) * BB + b] = xs[b * 81 + i];
        }
    }

    const int b0 = 2 * l, b1 = b0 + 1;
    const int len0 = __ldg(lengths + b0);
    const int len1 = __ldg(lengths + b1);
    const int myj  = j0 + w;                      // finalize: warp w owns column myj

    grid_barrier();                               // weights, h0, xT all visible

    const int kb  = w * KPW;
    const int i_b = w * IPW;

    for (int t = 0; t < T; ++t) {
        const int rb = t & 1, wb = rb ^ 1;
        const u64* __restrict__ hb = g_h[rb];

        u64 acc[HC];
        #pragma unroll
        for (int j = 0; j < HC; ++j) acc[j] = 0ull;

        // ---- input drive over my i-range ----
        {
            const u64* xt = (const u64*)g_xT + (size_t)(t * II + i_b) * (BB / 2) + l;
            #pragma unroll
            for (int u = 0; u < IPW; ++u) {
                u64 x2 = __ldg(xt + u * (BB / 2));
                const ulonglong2* wr = (const ulonglong2*)(Wihs + (i_b + u) * 8);
                ulonglong2 w01 = wr[0], w23 = wr[1], w45 = wr[2], w67 = wr[3];
                acc[0] = ffma2(x2, w01.x, acc[0]); acc[1] = ffma2(x2, w01.y, acc[1]);
                acc[2] = ffma2(x2, w23.x, acc[2]); acc[3] = ffma2(x2, w23.y, acc[3]);
                acc[4] = ffma2(x2, w45.x, acc[4]); acc[5] = ffma2(x2, w45.y, acc[5]);
                acc[6] = ffma2(x2, w67.x, acc[6]); acc[7] = ffma2(x2, w67.y, acc[7]);
            }
        }

        // ---- recurrent part over my k-range (double-buffered h loads) ----
        {
            const u64* hp = hb + (size_t)kb * (BB / 2) + l;
            u64 cur[8], nxt[8];
            #pragma unroll
            for (int u = 0; u < 8; ++u) cur[u] = __ldcg(hp + u * 32);
            for (int kt = 0; kt < KPW; kt += 8) {
                if (kt + 8 < KPW) {
                    #pragma unroll
                    for (int u = 0; u < 8; ++u) nxt[u] = __ldcg(hp + (kt + 8 + u) * 32);
                }
                #pragma unroll
                for (int u = 0; u < 8; ++u) {
                    const ulonglong2* wr = (const ulonglong2*)(Ws + (kb + kt + u) * 8);
                    ulonglong2 w01 = wr[0], w23 = wr[1], w45 = wr[2], w67 = wr[3];
                    u64 h2 = cur[u];
                    acc[0] = ffma2(h2, w01.x, acc[0]); acc[1] = ffma2(h2, w01.y, acc[1]);
                    acc[2] = ffma2(h2, w23.x, acc[2]); acc[3] = ffma2(h2, w23.y, acc[3]);
                    acc[4] = ffma2(h2, w45.x, acc[4]); acc[5] = ffma2(h2, w45.y, acc[5]);
                    acc[6] = ffma2(h2, w67.x, acc[6]); acc[7] = ffma2(h2, w67.y, acc[7]);
                }
                #pragma unroll
                for (int u = 0; u < 8; ++u) cur[u] = nxt[u];
            }
        }

        // ---- cross-warp reduce ----
        #pragma unroll
        for (int j = 0; j < HC; ++j) red[(w * 8 + j) * 32 + l] = acc[j];
        __syncthreads();

        // warp w finalizes column myj; lane l handles batch pair (b0,b1)
        {
            u64 s = red[(0 * 8 + w) * 32 + l];
            #pragma unroll
            for (int p = 1; p < NWARP; ++p) s = fadd2(s, red[(p * 8 + w) * 32 + l]);

            u64 hold = g_h[rb][myj * 32 + l];
            float h0v = lo2(hold), h1v = hi2(hold);
            float nh0 = h0v, nh1 = h1v;
            bool v0 = t < len0, v1 = t < len1;
            if (v0) nh0 = 0.5f * h0v + 0.5f * tanhf(lo2(s));
            if (v1) nh1 = 0.5f * h1v + 0.5f * tanhf(hi2(s));
            g_h[wb][myj * 32 + l] = pack2(nh0, nh1);

            outs[w * BB + b0] = v0 ? nh0 : 0.0f;
            outs[w * BB + b1] = v1 ? nh1 : 0.0f;
        }
        __syncthreads();

        // coalesced output store: out[t][b][j0+jj]
        {
            float* ob = out + (size_t)t * BB * HH + j0;
            #pragma unroll 2
            for (int idx = tid; idx < BB * HC; idx += NTHR) {
                int b = idx >> 3, jj = idx & 7;
                ob[(size_t)b * HH + jj] = outs[jj * BB + b];
            }
        }

        grid_barrier();   // h[wb] published before next step reads it
    }
}

extern "C" void kernel_launch(void* const* d_in, const int* in_sizes, int n_in,
                              void* d_out, int out_size) {
    const float* x       = (const float*)d_in[0];
    const int*   lengths = (const int*)d_in[1];
    const float* W_ih    = (const float*)d_in[2];
    const float* W_hh    = (const float*)d_in[3];
    float*       out     = (float*)d_out;
    int T = in_sizes[0] / (BB * II);

    cudaFuncSetAttribute(esn_kernel, cudaFuncAttributeMaxDynamicSharedMemorySize, SMEM_BYTES);
    esn_kernel<<<NCTA, NTHR, SMEM_BYTES>>>(x, lengths, W_ih, W_hh, out, T);
}

// round 7
// speedup vs baseline: 1.0253x; 1.0253x over previous
#include <cuda_runtime.h>
#include <cstdint>

// ESN recurrence, persistent kernel, v2 blocking.
// T=1000, B=64, I=80, H=1024, LEAK=0.5.
// Grid: 128 CTAs = 64 j-groups (16 cols) x 2 b-groups (32 batch).
// Lane tile: 4 j x 2 batch-pairs -> 8 FFMA2 per 3 L1 ops per k.
// h: double-buffered global, [buf][bg][k][16 bp] u64 (batch pair packed).

#define BB    64
#define II    80
#define HH    1024
#define NCTA  128
#define JC    16          // j columns per CTA
#define BPC   16          // batch-pairs per CTA (32 b)
#define NBG   2
#define NTHR  256
#define NWARP 8
#define KPW   (HH / NWARP)   // 128
#define IPW   (II / NWARP)   // 10
#define T_MAX 1024

typedef unsigned long long u64;

__device__ __align__(16) u64 g_h[2][NBG][HH][BPC];       // 512 KB
__device__ __align__(16) float g_xT[T_MAX * II * BB];    // [t][i][b]
__device__ unsigned g_bar_count = 0;
__device__ volatile unsigned g_bar_gen = 0;

__device__ __forceinline__ u64 ffma2(u64 a, u64 b, u64 c) {
    u64 d; asm("fma.rn.f32x2 %0, %1, %2, %3;" : "=l"(d) : "l"(a), "l"(b), "l"(c)); return d;
}
__device__ __forceinline__ u64 fadd2(u64 a, u64 b) {
    u64 d; asm("add.rn.f32x2 %0, %1, %2;" : "=l"(d) : "l"(a), "l"(b)); return d;
}
__device__ __forceinline__ u64 pack2(float lo, float hi) {
    u64 d; asm("mov.b64 %0, {%1, %2};" : "=l"(d) : "f"(lo), "f"(hi)); return d;
}
__device__ __forceinline__ float lo2(u64 v) { return __uint_as_float((unsigned)v); }
__device__ __forceinline__ float hi2(u64 v) { return __uint_as_float((unsigned)(v >> 32)); }

__device__ __forceinline__ void grid_barrier() {
    __syncthreads();
    if (threadIdx.x == 0) {
        __threadfence();
        unsigned g = g_bar_gen;                  // read BEFORE arriving
        if (atomicAdd(&g_bar_count, 1u) == gridDim.x - 1u) {
            g_bar_count = 0;
            __threadfence();
            g_bar_gen = g + 1u;
        } else {
            while (g_bar_gen == g) { }
        }
        __threadfence();
    }
    __syncthreads();
}

// dynamic SMEM:
//  [0,131072)        Ws   : W_hh slice [k][16 j] dup f32x2 (u64)
//  [131072,141312)   Wihs : W_ih slice [i][16 j] dup f32x2 (u64)
//  [141312,157696)   red  : [8 w][16 j][16 bp] u64        (union xs)
//  [157696,159744)   outs : [16 j][32 b] float            (union xs)
//  [141312,162048)   xs   : [64][81] float transpose scratch (staging only)
#define WS_OFF   0
#define WIH_OFF  131072
#define RED_OFF  141312
#define OUT_OFF  157696
#define XS_OFF   141312
#define SMEM_BYTES 162048

extern "C" __global__ void __launch_bounds__(NTHR, 1)
esn_kernel(const float* __restrict__ x, const int* __restrict__ lengths,
           const float* __restrict__ W_ih, const float* __restrict__ W_hh,
           float* __restrict__ out, int T)
{
    extern __shared__ unsigned char smem[];
    u64*   Ws   = (u64*)(smem + WS_OFF);
    u64*   Wihs = (u64*)(smem + WIH_OFF);
    u64*   red  = (u64*)(smem + RED_OFF);
    float* outs = (float*)(smem + OUT_OFF);
    float* xs   = (float*)(smem + XS_OFF);

    const int tid = threadIdx.x;
    const int w   = tid >> 5;
    const int l   = tid & 31;
    const int jf  = l >> 3;      // 0..3 -> j local {4jf..4jf+3}
    const int bq  = l & 7;       // 0..7 -> bp local {2bq,2bq+1}
    const int bx  = blockIdx.x;
    const int jg  = bx >> 1, bg = bx & 1;
    const int j0  = jg * JC;     // global column base
    const int b0  = bg * 32;     // global batch base

    // ---- one-time staging ----
    for (int idx = tid; idx < JC * HH; idx += NTHR) {
        int j = idx >> 10, k = idx & 1023;              // coalesced over k
        float v = W_hh[(size_t)(j0 + j) * HH + k];
        Ws[k * JC + j] = pack2(v, v);
    }
    for (int idx = tid; idx < II * JC; idx += NTHR) {
        int i = idx >> 4, j = idx & 15;
        float v = W_ih[(j0 + j) * II + i];
        Wihs[i * JC + j] = pack2(v, v);
    }
    for (int idx = tid; idx < JC * BPC; idx += NTHR)
        g_h[0][bg][j0 + (idx >> 4)][idx & 15] = 0ull;

    // transpose x[t][b][i] -> g_xT[t][i][b]
    for (int tt = blockIdx.x; tt < T; tt += NCTA) {
        __syncthreads();
        const float4* src = (const float4*)(x + (size_t)tt * BB * II);
        for (int idx = tid; idx < (BB * II) / 4; idx += NTHR) {
            float4 v = src[idx];
            int base = idx * 4;
            int b = base / II, i = base % II;
            float* dst = &xs[b * 81 + i];
            dst[0] = v.x; dst[1] = v.y; dst[2] = v.z; dst[3] = v.w;
        }
        __syncthreads();
        for (int idx = tid; idx < BB * II; idx += NTHR) {
            int i = idx >> 6, b = idx & 63;
            g_xT[((size_t)tt * II + i) * BB + b] = xs[b * 81 + i];
        }
    }

    // finalize-role constants: thread tid handles (fj, fb)
    const int fj = tid >> 4;          // 0..15 j local
    const int fb = tid & 15;          // 0..15 bp local
    const int gb = b0 + 2 * fb;
    const int len0 = __ldg(lengths + gb);
    const int len1 = __ldg(lengths + gb + 1);

    grid_barrier();                   // weights, h0, xT visible

    const int kb = w * KPW;

    for (int t = 0; t < T; ++t) {
        const int rb = t & 1, wb = rb ^ 1;

        // ---- fill h prefetch ring (8 deep) ----
        const u64* hp = &g_h[rb][bg][0][0] + (size_t)kb * BPC + 2 * bq;
        ulonglong2 ring[8];
        #pragma unroll
        for (int d = 0; d < 8; ++d)
            ring[d] = __ldcg((const ulonglong2*)(hp + d * BPC));

        u64 acc[4][2];
        #pragma unroll
        for (int jj = 0; jj < 4; ++jj) { acc[jj][0] = 0ull; acc[jj][1] = 0ull; }

        // ---- input drive over my i-range (covers ring-fill latency) ----
        {
            const float* xbase = g_xT + ((size_t)t * II + w * IPW) * BB + b0 + 4 * bq;
            const ulonglong2* wih = (const ulonglong2*)(Wihs + (size_t)(w * IPW) * JC) + 2 * jf;
            #pragma unroll
            for (int u = 0; u < IPW; ++u) {
                ulonglong2 x2 = *(const ulonglong2*)(xbase + u * BB);
                ulonglong2 wa = wih[u * 8];
                ulonglong2 wc = wih[u * 8 + 1];
                acc[0][0] = ffma2(x2.x, wa.x, acc[0][0]); acc[0][1] = ffma2(x2.y, wa.x, acc[0][1]);
                acc[1][0] = ffma2(x2.x, wa.y, acc[1][0]); acc[1][1] = ffma2(x2.y, wa.y, acc[1][1]);
                acc[2][0] = ffma2(x2.x, wc.x, acc[2][0]); acc[2][1] = ffma2(x2.y, wc.x, acc[2][1]);
                acc[3][0] = ffma2(x2.x, wc.y, acc[3][0]); acc[3][1] = ffma2(x2.y, wc.y, acc[3][1]);
            }
        }

        // ---- recurrent part: 8 FFMA2 per 3 L1 ops per k ----
        {
            const ulonglong2* wsp = (const ulonglong2*)(Ws + (size_t)kb * JC) + 2 * jf;
            #pragma unroll 8
            for (int kt = 0; kt < KPW; ++kt) {
                ulonglong2 h2 = ring[kt & 7];
                if (kt + 8 < KPW)
                    ring[kt & 7] = __ldcg((const ulonglong2*)(hp + (kt + 8) * BPC));
                ulonglong2 wa = wsp[kt * 8];
                ulonglong2 wc = wsp[kt * 8 + 1];
                acc[0][0] = ffma2(h2.x, wa.x, acc[0][0]); acc[0][1] = ffma2(h2.y, wa.x, acc[0][1]);
                acc[1][0] = ffma2(h2.x, wa.y, acc[1][0]); acc[1][1] = ffma2(h2.y, wa.y, acc[1][1]);
                acc[2][0] = ffma2(h2.x, wc.x, acc[2][0]); acc[2][1] = ffma2(h2.y, wc.x, acc[2][1]);
                acc[3][0] = ffma2(h2.x, wc.y, acc[3][0]); acc[3][1] = ffma2(h2.y, wc.y, acc[3][1]);
            }
        }

        // prefetch old h for my finalize slot (hides L2 latency behind sync)
        u64 hold = __ldcg(&g_h[rb][bg][j0 + fj][fb]);

        // ---- write partials ----
        #pragma unroll
        for (int jj = 0; jj < 4; ++jj) {
            *(ulonglong2*)(red + ((size_t)(w * JC + 4 * jf + jj) * BPC + 2 * bq)) =
                make_ulonglong2(acc[jj][0], acc[jj][1]);
        }
        __syncthreads();

        // ---- finalize: thread = (fj, fb) ----
        {
            u64 s = red[(size_t)(0 * JC + fj) * BPC + fb];
            #pragma unroll
            for (int p = 1; p < NWARP; ++p)
                s = fadd2(s, red[(size_t)(p * JC + fj) * BPC + fb]);

            float h0v = lo2(hold), h1v = hi2(hold);
            float nh0 = h0v, nh1 = h1v;
            bool v0 = t < len0, v1 = t < len1;
            if (v0) nh0 = 0.5f * h0v + 0.5f * tanhf(lo2(s));
            if (v1) nh1 = 0.5f * h1v + 0.5f * tanhf(hi2(s));
            g_h[wb][bg][j0 + fj][fb] = pack2(nh0, nh1);

            outs[fj * 32 + 2 * fb]     = v0 ? nh0 : 0.0f;
            outs[fj * 32 + 2 * fb + 1] = v1 ? nh1 : 0.0f;
        }
        __syncthreads();

        // ---- coalesced output store: out[t][b0+bl][j0+jj] ----
        {
            float* ob = out + ((size_t)t * BB + b0) * HH + j0;
            #pragma unroll 2
            for (int idx = tid; idx < 32 * JC; idx += NTHR) {
                int bl = idx >> 4, jj = idx & 15;
                ob[(size_t)bl * HH + jj] = outs[jj * 32 + bl];
            }
        }

        grid_barrier();
    }
}

extern "C" void kernel_launch(void* const* d_in, const int* in_sizes, int n_in,
                              void* d_out, int out_size) {
    const float* x       = (const float*)d_in[0];
    const int*   lengths = (const int*)d_in[1];
    const float* W_ih    = (const float*)d_in[2];
    const float* W_hh    = (const float*)d_in[3];
    float*       out     = (float*)d_out;
    int T = in_sizes[0] / (BB * II);

    cudaFuncSetAttribute(esn_kernel, cudaFuncAttributeMaxDynamicSharedMemorySize, SMEM_BYTES);
    esn_kernel<<<NCTA, NTHR, SMEM_BYTES>>>(x, lengths, W_ih, W_hh, out, T);
}

// round 8
// speedup vs baseline: 1.0694x; 1.0430x over previous
#include <cuda_runtime.h>
#include <cstdint>

// ESN recurrence, persistent kernel, v3: 512 threads/CTA for latency hiding.
// T=1000, B=64, I=80, H=1024, LEAK=0.5.
// Grid: 128 CTAs = 64 j-groups (16 cols) x 2 b-groups (32 batch).
// 16 warps split K (64 k each); lane tile 4 j x 2 batch-pairs, f32x2 packed.

#define BB    64
#define II    80
#define HH    1024
#define NCTA  128
#define JC    16
#define BPC   16
#define NBG   2
#define NTHR  512
#define NWARP 16
#define KPW   (HH / NWARP)   // 64
#define IPW   (II / NWARP)   // 5
#define T_MAX 1024

typedef unsigned long long u64;

__device__ __align__(16) u64 g_h[2][NBG][HH][BPC];
__device__ __align__(16) float g_xT[T_MAX * II * BB];   // [t][i][b]
__device__ unsigned g_bar_count = 0;
__device__ volatile unsigned g_bar_gen = 0;

__device__ __forceinline__ u64 ffma2(u64 a, u64 b, u64 c) {
    u64 d; asm("fma.rn.f32x2 %0, %1, %2, %3;" : "=l"(d) : "l"(a), "l"(b), "l"(c)); return d;
}
__device__ __forceinline__ u64 fadd2(u64 a, u64 b) {
    u64 d; asm("add.rn.f32x2 %0, %1, %2;" : "=l"(d) : "l"(a), "l"(b)); return d;
}
__device__ __forceinline__ u64 pack2(float lo, float hi) {
    u64 d; asm("mov.b64 %0, {%1, %2};" : "=l"(d) : "f"(lo), "f"(hi)); return d;
}
__device__ __forceinline__ float lo2(u64 v) { return __uint_as_float((unsigned)v); }
__device__ __forceinline__ float hi2(u64 v) { return __uint_as_float((unsigned)(v >> 32)); }

__device__ __forceinline__ void grid_barrier() {
    __syncthreads();
    if (threadIdx.x == 0) {
        __threadfence();
        unsigned g = g_bar_gen;                  // read BEFORE arriving
        if (atomicAdd(&g_bar_count, 1u) == gridDim.x - 1u) {
            g_bar_count = 0;
            __threadfence();
            g_bar_gen = g + 1u;
        } else {
            while (g_bar_gen == g) { }
        }
        __threadfence();
    }
    __syncthreads();
}

// dynamic SMEM:
//  [0,131072)        Ws   : W_hh slice [k][16 j] dup f32x2 (u64)
//  [131072,141312)   Wihs : W_ih slice [i][16 j] dup f32x2 (u64)
//  [141312,174080)   red  : [16 w][16 j][16 bp] u64       (union xs)
//  [174080,176128)   outs : [16 j][32 b] float
//  [141312,162048)   xs   : [64][81] float transpose scratch (staging only)
#define WS_OFF   0
#define WIH_OFF  131072
#define RED_OFF  141312
#define OUT_OFF  174080
#define XS_OFF   141312
#define SMEM_BYTES 176128

extern "C" __global__ void __launch_bounds__(NTHR, 1)
esn_kernel(const float* __restrict__ x, const int* __restrict__ lengths,
           const float* __restrict__ W_ih, const float* __restrict__ W_hh,
           float* __restrict__ out, int T)
{
    extern __shared__ unsigned char smem[];
    u64*   Ws   = (u64*)(smem + WS_OFF);
    u64*   Wihs = (u64*)(smem + WIH_OFF);
    u64*   red  = (u64*)(smem + RED_OFF);
    float* outs = (float*)(smem + OUT_OFF);
    float* xs   = (float*)(smem + XS_OFF);

    const int tid = threadIdx.x;
    const int w   = tid >> 5;
    const int l   = tid & 31;
    const int jf  = l >> 3;      // 0..3 -> j local {4jf..4jf+3}
    const int bq  = l & 7;       // 0..7 -> bp local {2bq,2bq+1}
    const int bx  = blockIdx.x;
    const int jg  = bx >> 1, bg = bx & 1;
    const int j0  = jg * JC;
    const int b0  = bg * 32;

    // ---- one-time staging ----
    for (int idx = tid; idx < JC * HH; idx += NTHR) {
        int j = idx >> 10, k = idx & 1023;            // coalesced over k
        float v = W_hh[(size_t)(j0 + j) * HH + k];
        Ws[k * JC + j] = pack2(v, v);
    }
    for (int idx = tid; idx < II * JC; idx += NTHR) {
        int i = idx >> 4, j = idx & 15;
        float v = W_ih[(j0 + j) * II + i];
        Wihs[i * JC + j] = pack2(v, v);
    }
    if (tid < JC * BPC)
        g_h[0][bg][j0 + (tid >> 4)][tid & 15] = 0ull;

    // transpose x[t][b][i] -> g_xT[t][i][b]
    for (int tt = blockIdx.x; tt < T; tt += NCTA) {
        __syncthreads();
        const float4* src = (const float4*)(x + (size_t)tt * BB * II);
        for (int idx = tid; idx < (BB * II) / 4; idx += NTHR) {
            float4 v = src[idx];
            int base = idx * 4;
            int b = base / II, i = base % II;
            float* dst = &xs[b * 81 + i];
            dst[0] = v.x; dst[1] = v.y; dst[2] = v.z; dst[3] = v.w;
        }
        __syncthreads();
        for (int idx = tid; idx < BB * II; idx += NTHR) {
            int i = idx >> 6, b = idx & 63;
            g_xT[((size_t)tt * II + i) * BB + b] = xs[b * 81 + i];
        }
    }

    // finalize role (first 256 threads): thread = (fj, fb)
    const int fj = (tid >> 4) & 15;
    const int fb = tid & 15;
    const int gb = b0 + 2 * fb;
    const int len0 = __ldg(lengths + gb);
    const int len1 = __ldg(lengths + gb + 1);

    grid_barrier();                   // weights, h0, xT visible

    const int kb = w * KPW;

    for (int t = 0; t < T; ++t) {
        const int rb = t & 1, wb = rb ^ 1;

        // ---- fill h prefetch ring (8 deep) ----
        const u64* hp = &g_h[rb][bg][0][0] + (size_t)kb * BPC + 2 * bq;
        ulonglong2 ring[8];
        #pragma unroll
        for (int d = 0; d < 8; ++d)
            ring[d] = __ldcg((const ulonglong2*)(hp + d * BPC));

        u64 acc[4][2];
        #pragma unroll
        for (int jj = 0; jj < 4; ++jj) { acc[jj][0] = 0ull; acc[jj][1] = 0ull; }

        // ---- input drive over my i-range (covers ring-fill latency) ----
        {
            const float* xbase = g_xT + ((size_t)t * II + w * IPW) * BB + b0 + 4 * bq;
            const ulonglong2* wih = (const ulonglong2*)(Wihs + (size_t)(w * IPW) * JC) + 2 * jf;
            #pragma unroll
            for (int u = 0; u < IPW; ++u) {
                ulonglong2 x2 = *(const ulonglong2*)(xbase + u * BB);
                ulonglong2 wa = wih[u * 8];
                ulonglong2 wc = wih[u * 8 + 1];
                acc[0][0] = ffma2(x2.x, wa.x, acc[0][0]); acc[0][1] = ffma2(x2.y, wa.x, acc[0][1]);
                acc[1][0] = ffma2(x2.x, wa.y, acc[1][0]); acc[1][1] = ffma2(x2.y, wa.y, acc[1][1]);
                acc[2][0] = ffma2(x2.x, wc.x, acc[2][0]); acc[2][1] = ffma2(x2.y, wc.x, acc[2][1]);
                acc[3][0] = ffma2(x2.x, wc.y, acc[3][0]); acc[3][1] = ffma2(x2.y, wc.y, acc[3][1]);
            }
        }

        // ---- recurrent part: 8 FFMA2 per 3 L1 ops per k ----
        {
            const ulonglong2* wsp = (const ulonglong2*)(Ws + (size_t)kb * JC) + 2 * jf;
            #pragma unroll 8
            for (int kt = 0; kt < KPW; ++kt) {
                ulonglong2 h2 = ring[kt & 7];
                if (kt + 8 < KPW)
                    ring[kt & 7] = __ldcg((const ulonglong2*)(hp + (kt + 8) * BPC));
                ulonglong2 wa = wsp[kt * 8];
                ulonglong2 wc = wsp[kt * 8 + 1];
                acc[0][0] = ffma2(h2.x, wa.x, acc[0][0]); acc[0][1] = ffma2(h2.y, wa.x, acc[0][1]);
                acc[1][0] = ffma2(h2.x, wa.y, acc[1][0]); acc[1][1] = ffma2(h2.y, wa.y, acc[1][1]);
                acc[2][0] = ffma2(h2.x, wc.x, acc[2][0]); acc[2][1] = ffma2(h2.y, wc.x, acc[2][1]);
                acc[3][0] = ffma2(h2.x, wc.y, acc[3][0]); acc[3][1] = ffma2(h2.y, wc.y, acc[3][1]);
            }
        }

        // prefetch old h for finalize slot (hides L2 latency behind sync)
        u64 hold = 0ull;
        if (tid < 256) hold = __ldcg(&g_h[rb][bg][j0 + fj][fb]);

        // ---- write partials ----
        #pragma unroll
        for (int jj = 0; jj < 4; ++jj) {
            *(ulonglong2*)(red + ((size_t)(w * JC + 4 * jf + jj) * BPC + 2 * bq)) =
                make_ulonglong2(acc[jj][0], acc[jj][1]);
        }
        __syncthreads();

        // ---- finalize (256 threads): 16-way reduce + tanh + h update ----
        if (tid < 256) {
            u64 s = red[(size_t)(0 * JC + fj) * BPC + fb];
            #pragma unroll
            for (int p = 1; p < NWARP; ++p)
                s = fadd2(s, red[(size_t)(p * JC + fj) * BPC + fb]);

            float h0v = lo2(hold), h1v = hi2(hold);
            float nh0 = h0v, nh1 = h1v;
            bool v0 = t < len0, v1 = t < len1;
            if (v0) nh0 = 0.5f * h0v + 0.5f * tanhf(lo2(s));
            if (v1) nh1 = 0.5f * h1v + 0.5f * tanhf(hi2(s));
            g_h[wb][bg][j0 + fj][fb] = pack2(nh0, nh1);

            outs[fj * 32 + 2 * fb]     = v0 ? nh0 : 0.0f;
            outs[fj * 32 + 2 * fb + 1] = v1 ? nh1 : 0.0f;
        }
        __syncthreads();

        // ---- coalesced output store: 512 elems, 1 per thread ----
        {
            float* ob = out + ((size_t)t * BB + b0) * HH + j0;
            int bl = tid >> 4, jj = tid & 15;
            ob[(size_t)bl * HH + jj] = outs[jj * 32 + bl];
        }

        grid_barrier();
    }
}

extern "C" void kernel_launch(void* const* d_in, const int* in_sizes, int n_in,
                              void* d_out, int out_size) {
    const float* x       = (const float*)d_in[0];
    const int*   lengths = (const int*)d_in[1];
    const float* W_ih    = (const float*)d_in[2];
    const float* W_hh    = (const float*)d_in[3];
    float*       out     = (float*)d_out;
    int T = in_sizes[0] / (BB * II);

    cudaFuncSetAttribute(esn_kernel, cudaFuncAttributeMaxDynamicSharedMemorySize, SMEM_BYTES);
    esn_kernel<<<NCTA, NTHR, SMEM_BYTES>>>(x, lengths, W_ih, W_hh, out, T);
}